// round 9
// baseline (speedup 1.0000x reference)
#include <cuda_runtime.h>
#include <math.h>

#define BATCH     262144
#define MARGIN    1.0f
#define EPS_V     1e-6f

// 16B vector load, non-coherent, L2 evict_last policy (measured ~neutral to
// +1us warm; kept because it never hurt the 256-block shape).
__device__ __forceinline__ float4 ldg_el(const float4* p) {
    float4 v;
    asm volatile(
        "{\n\t"
        ".reg .b64 pol;\n\t"
        "createpolicy.fractional.L2::evict_last.b64 pol, 1.0;\n\t"
        "ld.global.nc.L2::cache_hint.v4.f32 {%0,%1,%2,%3}, [%4], pol;\n\t"
        "}"
        : "=f"(v.x), "=f"(v.y), "=f"(v.z), "=f"(v.w)
        : "l"(p));
    return v;
}

__device__ __forceinline__ float dot4(float4 a, float4 b) {
    return fmaf(a.x, b.x, fmaf(a.y, b.y, fmaf(a.z, b.z, a.w * b.w)));
}

// One warp per triple; even warp = pos, odd warp = neg of the same element.
// 128-thread blocks (4 warps, 2 elements): finest barrier granularity while
// keeping 64 warps/SM (16 blocks x 4 warps, regs ~30).
__global__ __launch_bounds__(128, 16)
void transd_kernel(const float* __restrict__ ent,
                   const float* __restrict__ entp,
                   const float* __restrict__ rel,
                   const float* __restrict__ relp,
                   const int*   __restrict__ pos,
                   const int*   __restrict__ neg,
                   float*       __restrict__ out)
{
    const int lane = threadIdx.x & 31;
    const int warp = threadIdx.x >> 5;          // 0..3
    const int pair = warp >> 1;                 // 0..1
    const int elem = blockIdx.x * 2 + pair;     // batch element
    const bool is_neg = warp & 1;

    const int* __restrict__ tri = is_neg ? neg : pos;
    const int h = tri[elem * 3 + 0];
    const int r = tri[elem * 3 + 1];
    const int t = tri[elem * 3 + 2];

    const size_t lo = (size_t)lane;
    const float4* E  = (const float4*)ent;
    const float4* EP = (const float4*)entp;
    const float4* R  = (const float4*)rel;
    const float4* RP = (const float4*)relp;

    // all 6 gathers issued up front (MLP); entity rows get evict_last
    float4 vh  = ldg_el(E  + (size_t)h * 32 + lo);
    float4 vhp = ldg_el(EP + (size_t)h * 32 + lo);
    float4 vt  = ldg_el(E  + (size_t)t * 32 + lo);
    float4 vtp = ldg_el(EP + (size_t)t * 32 + lo);
    float4 vr  = __ldg(R  + (size_t)r * 32 + lo);
    float4 vrp = __ldg(RP + (size_t)r * 32 + lo);

    // two dot partials, fused butterfly
    float sh = dot4(vhp, vh);
    float st = dot4(vtp, vt);
    #pragma unroll
    for (int o = 16; o > 0; o >>= 1) {
        sh += __shfl_xor_sync(0xFFFFFFFFu, sh, o);
        st += __shfl_xor_sync(0xFFFFFFFFu, st, o);
    }
    const float ds = sh - st;

    float dx = fmaf(vrp.x, ds, vh.x - vt.x + vr.x + EPS_V);
    float dy = fmaf(vrp.y, ds, vh.y - vt.y + vr.y + EPS_V);
    float dz = fmaf(vrp.z, ds, vh.z - vt.z + vr.z + EPS_V);
    float dw = fmaf(vrp.w, ds, vh.w - vt.w + vr.w + EPS_V);

    float ss = dx*dx + dy*dy + dz*dz + dw*dw;
    #pragma unroll
    for (int o = 16; o > 0; o >>= 1)
        ss += __shfl_xor_sync(0xFFFFFFFFu, ss, o);

    const float score = sqrtf(ss);

    __shared__ float scores[4];
    if (lane == 0) scores[warp] = score;
    __syncthreads();

    if (warp == 0) {
        float s = 0.0f;
        if (lane < 2) {
            float loss = scores[2 * lane] - scores[2 * lane + 1] + MARGIN;
            s = loss > 0.0f ? loss : 0.0f;
        }
        s += __shfl_xor_sync(0xFFFFFFFFu, s, 1);
        if (lane == 0)
            atomicAdd(out, s * (1.0f / (float)BATCH));
    }
}

extern "C" void kernel_launch(void* const* d_in, const int* in_sizes, int n_in,
                              void* d_out, int out_size)
{
    const float* ent   = (const float*)d_in[0];
    const float* entp  = (const float*)d_in[1];
    const float* rel   = (const float*)d_in[2];
    const float* relp  = (const float*)d_in[3];
    const int*   pos_x = (const int*)d_in[4];
    const int*   neg_x = (const int*)d_in[5];
    float*       out   = (float*)d_out;

    cudaMemsetAsync(out, 0, sizeof(float));

    const int blocks = BATCH / 2;  // 2 elements per block, 4 warps
    transd_kernel<<<blocks, 128>>>(ent, entp, rel, relp, pos_x, neg_x, out);
}

// round 10
// speedup vs baseline: 2.6077x; 2.6077x over previous
#include <cuda_runtime.h>
#include <math.h>

#define BATCH     262144
#define MARGIN    1.0f
#define EPS_V     1e-6f
#define NBLOCKS   (BATCH / 4)   // 65536 main-kernel blocks

// block partial sums (scratch; every slot rewritten each launch)
__device__ float g_partial[NBLOCKS];

// 16B vector load, non-coherent, L2 evict_last policy.
__device__ __forceinline__ float4 ldg_el(const float4* p) {
    float4 v;
    asm volatile(
        "{\n\t"
        ".reg .b64 pol;\n\t"
        "createpolicy.fractional.L2::evict_last.b64 pol, 1.0;\n\t"
        "ld.global.nc.L2::cache_hint.v4.f32 {%0,%1,%2,%3}, [%4], pol;\n\t"
        "}"
        : "=f"(v.x), "=f"(v.y), "=f"(v.z), "=f"(v.w)
        : "l"(p));
    return v;
}

__device__ __forceinline__ float dot4(float4 a, float4 b) {
    return fmaf(a.x, b.x, fmaf(a.y, b.y, fmaf(a.z, b.z, a.w * b.w)));
}

// One warp per triple; even warp = pos, odd warp = neg of the same element.
// 256 threads (8 warps, 4 elements) x 8 blocks/SM = 64 warps/SM. Block
// writes ONE coalesced partial instead of a same-address atomic.
__global__ __launch_bounds__(256, 8)
void transd_kernel(const float* __restrict__ ent,
                   const float* __restrict__ entp,
                   const float* __restrict__ rel,
                   const float* __restrict__ relp,
                   const int*   __restrict__ pos,
                   const int*   __restrict__ neg)
{
    const int lane = threadIdx.x & 31;
    const int warp = threadIdx.x >> 5;          // 0..7
    const int pair = warp >> 1;                 // 0..3
    const int elem = blockIdx.x * 4 + pair;     // batch element
    const bool is_neg = warp & 1;

    const int* __restrict__ tri = is_neg ? neg : pos;
    const int h = tri[elem * 3 + 0];
    const int r = tri[elem * 3 + 1];
    const int t = tri[elem * 3 + 2];

    const size_t lo = (size_t)lane;
    const float4* E  = (const float4*)ent;
    const float4* EP = (const float4*)entp;
    const float4* R  = (const float4*)rel;
    const float4* RP = (const float4*)relp;

    // all 6 gathers issued up front (MLP); entity rows get evict_last
    float4 vh  = ldg_el(E  + (size_t)h * 32 + lo);
    float4 vhp = ldg_el(EP + (size_t)h * 32 + lo);
    float4 vt  = ldg_el(E  + (size_t)t * 32 + lo);
    float4 vtp = ldg_el(EP + (size_t)t * 32 + lo);
    float4 vr  = __ldg(R  + (size_t)r * 32 + lo);
    float4 vrp = __ldg(RP + (size_t)r * 32 + lo);

    // two dot partials, fused butterfly
    float sh = dot4(vhp, vh);
    float st = dot4(vtp, vt);
    #pragma unroll
    for (int o = 16; o > 0; o >>= 1) {
        sh += __shfl_xor_sync(0xFFFFFFFFu, sh, o);
        st += __shfl_xor_sync(0xFFFFFFFFu, st, o);
    }
    const float ds = sh - st;

    float dx = fmaf(vrp.x, ds, vh.x - vt.x + vr.x + EPS_V);
    float dy = fmaf(vrp.y, ds, vh.y - vt.y + vr.y + EPS_V);
    float dz = fmaf(vrp.z, ds, vh.z - vt.z + vr.z + EPS_V);
    float dw = fmaf(vrp.w, ds, vh.w - vt.w + vr.w + EPS_V);

    float ss = dx*dx + dy*dy + dz*dz + dw*dw;
    #pragma unroll
    for (int o = 16; o > 0; o >>= 1)
        ss += __shfl_xor_sync(0xFFFFFFFFu, ss, o);

    const float score = sqrtf(ss);

    __shared__ float scores[8];
    if (lane == 0) scores[warp] = score;
    __syncthreads();

    if (warp == 0) {
        float s = 0.0f;
        if (lane < 4) {
            float loss = scores[2 * lane] - scores[2 * lane + 1] + MARGIN;
            s = loss > 0.0f ? loss : 0.0f;
        }
        #pragma unroll
        for (int o = 2; o > 0; o >>= 1)
            s += __shfl_xor_sync(0xFFFFFFFFu, s, o);
        if (lane == 0)
            g_partial[blockIdx.x] = s;   // coalesced store, no atomic
    }
}

// Second stage: reduce 65536 partials -> scalar. 128 blocks x 512 threads,
// one element per thread, 128 atomics total.
__global__ __launch_bounds__(512)
void reduce_kernel(float* __restrict__ out)
{
    const int lane = threadIdx.x & 31;
    const int warp = threadIdx.x >> 5;   // 0..15
    const int idx  = blockIdx.x * 512 + threadIdx.x;

    float s = g_partial[idx];
    #pragma unroll
    for (int o = 16; o > 0; o >>= 1)
        s += __shfl_xor_sync(0xFFFFFFFFu, s, o);

    __shared__ float smem[16];
    if (lane == 0) smem[warp] = s;
    __syncthreads();

    if (warp == 0) {
        float v = (lane < 16) ? smem[lane] : 0.0f;
        #pragma unroll
        for (int o = 8; o > 0; o >>= 1)
            v += __shfl_xor_sync(0xFFFFFFFFu, v, o);
        if (lane == 0)
            atomicAdd(out, v * (1.0f / (float)BATCH));
    }
}

extern "C" void kernel_launch(void* const* d_in, const int* in_sizes, int n_in,
                              void* d_out, int out_size)
{
    const float* ent   = (const float*)d_in[0];
    const float* entp  = (const float*)d_in[1];
    const float* rel   = (const float*)d_in[2];
    const float* relp  = (const float*)d_in[3];
    const int*   pos_x = (const int*)d_in[4];
    const int*   neg_x = (const int*)d_in[5];
    float*       out   = (float*)d_out;

    cudaMemsetAsync(out, 0, sizeof(float));
    transd_kernel<<<NBLOCKS, 256>>>(ent, entp, rel, relp, pos_x, neg_x);
    reduce_kernel<<<NBLOCKS / 512, 512>>>(out);
}

// round 11
// speedup vs baseline: 2.7125x; 1.0402x over previous
#include <cuda_runtime.h>
#include <math.h>

#define BATCH     262144
#define MARGIN    1.0f
#define EPS_V     1e-6f

__device__ __forceinline__ float dot4(float4 a, float4 b) {
    return fmaf(a.x, b.x, fmaf(a.y, b.y, fmaf(a.z, b.z, a.w * b.w)));
}

// One warp per triple; even warp = pos, odd warp = neg of the same element.
// 256 threads (8 warps, 4 elements) x 8 blocks/SM = 64 warps/SM resident.
// Plain __ldg (no cache-policy asm): fewer issue slots in the load burst.
__global__ __launch_bounds__(256, 8)
void transd_kernel(const float* __restrict__ ent,
                   const float* __restrict__ entp,
                   const float* __restrict__ rel,
                   const float* __restrict__ relp,
                   const int*   __restrict__ pos,
                   const int*   __restrict__ neg,
                   float*       __restrict__ out)
{
    const int lane = threadIdx.x & 31;
    const int warp = threadIdx.x >> 5;          // 0..7
    const int pair = warp >> 1;                 // 0..3
    const int elem = blockIdx.x * 4 + pair;     // batch element
    const bool is_neg = warp & 1;

    const int* __restrict__ tri = is_neg ? neg : pos;
    const int h = tri[elem * 3 + 0];
    const int r = tri[elem * 3 + 1];
    const int t = tri[elem * 3 + 2];

    const size_t lo = (size_t)lane;
    const float4* E  = (const float4*)ent;
    const float4* EP = (const float4*)entp;
    const float4* R  = (const float4*)rel;
    const float4* RP = (const float4*)relp;

    // all 6 gathers issued up front (MLP)
    float4 vh  = __ldg(E  + (size_t)h * 32 + lo);
    float4 vhp = __ldg(EP + (size_t)h * 32 + lo);
    float4 vt  = __ldg(E  + (size_t)t * 32 + lo);
    float4 vtp = __ldg(EP + (size_t)t * 32 + lo);
    float4 vr  = __ldg(R  + (size_t)r * 32 + lo);
    float4 vrp = __ldg(RP + (size_t)r * 32 + lo);

    // two dot partials, fused butterfly
    float sh = dot4(vhp, vh);
    float st = dot4(vtp, vt);
    #pragma unroll
    for (int o = 16; o > 0; o >>= 1) {
        sh += __shfl_xor_sync(0xFFFFFFFFu, sh, o);
        st += __shfl_xor_sync(0xFFFFFFFFu, st, o);
    }
    const float ds = sh - st;

    float dx = fmaf(vrp.x, ds, vh.x - vt.x + vr.x + EPS_V);
    float dy = fmaf(vrp.y, ds, vh.y - vt.y + vr.y + EPS_V);
    float dz = fmaf(vrp.z, ds, vh.z - vt.z + vr.z + EPS_V);
    float dw = fmaf(vrp.w, ds, vh.w - vt.w + vr.w + EPS_V);

    float ss = dx*dx + dy*dy + dz*dz + dw*dw;
    #pragma unroll
    for (int o = 16; o > 0; o >>= 1)
        ss += __shfl_xor_sync(0xFFFFFFFFu, ss, o);

    const float score = sqrtf(ss);

    __shared__ float scores[8];
    if (lane == 0) scores[warp] = score;
    __syncthreads();

    if (warp == 0) {
        float s = 0.0f;
        if (lane < 4) {
            float loss = scores[2 * lane] - scores[2 * lane + 1] + MARGIN;
            s = loss > 0.0f ? loss : 0.0f;
        }
        #pragma unroll
        for (int o = 2; o > 0; o >>= 1)
            s += __shfl_xor_sync(0xFFFFFFFFu, s, o);
        if (lane == 0)
            atomicAdd(out, s * (1.0f / (float)BATCH));
    }
}

extern "C" void kernel_launch(void* const* d_in, const int* in_sizes, int n_in,
                              void* d_out, int out_size)
{
    const float* ent   = (const float*)d_in[0];
    const float* entp  = (const float*)d_in[1];
    const float* rel   = (const float*)d_in[2];
    const float* relp  = (const float*)d_in[3];
    const int*   pos_x = (const int*)d_in[4];
    const int*   neg_x = (const int*)d_in[5];
    float*       out   = (float*)d_out;

    cudaMemsetAsync(out, 0, sizeof(float));

    const int blocks = BATCH / 4;  // 4 elements per block, 8 warps
    transd_kernel<<<blocks, 256>>>(ent, entp, rel, relp, pos_x, neg_x, out);
}